// round 3
// baseline (speedup 1.0000x reference)
#include <cuda_runtime.h>
#include <cuda_bf16.h>
#include <stdint.h>

// GCNProtein: 6-layer GCN, 1M nodes, 16M edges, dims 1->3->3->3->3->3->1.
// Round 3: build dst-sorted edge list once (hist+scan+scatter into packed
// (src,dst) int2 pairs). Layer passes stay flat edge-parallel (the shape that
// measured fast), but each thread takes 8 consecutive sorted edges, combines
// same-dst runs in registers, and emits ~1.44 red.global per 8 edges instead
// of 8 — atomic lanes drop ~5.5x vs round 1.

#define NMAX 1000000
#define EMAX 16000000
#define SCAN_ITEMS 16
#define SCAN_THREADS 256
#define SCAN_BLOCK_ELEMS (SCAN_ITEMS * SCAN_THREADS)   // 4096
#define MAX_SCAN_BLOCKS 256

__device__ float  g_x1[NMAX];        // scalar messages (layers 1, 6)
__device__ float  g_agg1[NMAX];
__device__ float4 g_x3a[NMAX];       // 3-wide messages, double buffered
__device__ float4 g_x3b[NMAX];
__device__ float4 g_agg3[NMAX];
__device__ int    g_cnt[NMAX];
__device__ int    g_off[NMAX + 1];
__device__ int    g_cursor[NMAX];
__device__ int4   g_ed4[EMAX / 2];   // packed (src,dst) pairs, dst-sorted; int4 = 2 edges
__device__ int    g_bsum[MAX_SCAN_BLOCKS];
__device__ int    g_bsum2[MAX_SCAN_BLOCKS];

__device__ __forceinline__ void red_add_f32(float* p, float v) {
    asm volatile("red.global.add.f32 [%0], %1;" :: "l"(p), "f"(v) : "memory");
}
__device__ __forceinline__ void red_add_v2_f32(float* p, float x, float y) {
    asm volatile("red.global.add.v2.f32 [%0], {%1, %2};" :: "l"(p), "f"(x), "f"(y) : "memory");
}

// ---------------- build phase ----------------

__global__ void k_init(const float* __restrict__ feat, const float* __restrict__ norm, int n) {
    int i = blockIdx.x * blockDim.x + threadIdx.x;
    if (i < n) {
        g_x1[i] = feat[i] * norm[i];
        g_agg1[i] = 0.f;
        g_agg3[i] = make_float4(0.f, 0.f, 0.f, 0.f);
        g_cnt[i] = 0;
    }
}

__global__ void k_hist(const int* __restrict__ dst, int E) {
    int e = blockIdx.x * blockDim.x + threadIdx.x;
    if (e < E) atomicAdd(&g_cnt[dst[e]], 1);
}

__global__ void k_scanA(int n) {
    int tid = threadIdx.x;
    int base = blockIdx.x * SCAN_BLOCK_ELEMS + tid * SCAN_ITEMS;
    int loc[SCAN_ITEMS];
    int s = 0;
#pragma unroll
    for (int k = 0; k < SCAN_ITEMS; k++) {
        int idx = base + k;
        int v = (idx < n) ? g_cnt[idx] : 0;
        loc[k] = s; s += v;
    }
    int lane = tid & 31, wid = tid >> 5;
    int x = s;
#pragma unroll
    for (int o = 1; o < 32; o <<= 1) {
        int y = __shfl_up_sync(0xFFFFFFFFu, x, o);
        if (lane >= o) x += y;
    }
    __shared__ int wsum[8];
    if (lane == 31) wsum[wid] = x;
    __syncthreads();
    int woff = 0;
    for (int w = 0; w < wid; w++) woff += wsum[w];
    int excl = woff + x - s;
#pragma unroll
    for (int k = 0; k < SCAN_ITEMS; k++) {
        int idx = base + k;
        if (idx < n) g_off[idx] = excl + loc[k];
    }
    if (tid == SCAN_THREADS - 1) g_bsum[blockIdx.x] = woff + x;
}

__global__ void k_scanB(int nb) {
    int tid = threadIdx.x;
    int v = (tid < nb) ? g_bsum[tid] : 0;
    int lane = tid & 31, wid = tid >> 5;
    int x = v;
#pragma unroll
    for (int o = 1; o < 32; o <<= 1) {
        int y = __shfl_up_sync(0xFFFFFFFFu, x, o);
        if (lane >= o) x += y;
    }
    __shared__ int wsum[8];
    if (lane == 31) wsum[wid] = x;
    __syncthreads();
    int woff = 0;
    for (int w = 0; w < wid; w++) woff += wsum[w];
    if (tid < nb) g_bsum2[tid] = woff + x - v;
}

__global__ void k_scanC(int n, int E) {
    int i = blockIdx.x * blockDim.x + threadIdx.x;
    if (i < n) {
        int o = g_off[i] + g_bsum2[i / SCAN_BLOCK_ELEMS];
        g_off[i] = o;
        g_cursor[i] = o;
    }
    if (i == 0) g_off[n] = E;
}

// place (src,dst) of each edge into its dst's segment as a packed int2
__global__ void k_scatter(const int* __restrict__ src, const int* __restrict__ dst, int E) {
    int e = blockIdx.x * blockDim.x + threadIdx.x;
    if (e >= E) return;
    int d = dst[e];
    int pos = atomicAdd(&g_cursor[d], 1);
    reinterpret_cast<int2*>(g_ed4)[pos] = make_int2(src[e], d);
}

// ---------------- edge kernels (8 sorted edges / thread, run-combined reds) ----

__global__ void k_edge_v8(const float4* __restrict__ xin, int E) {
    int t = blockIdx.x * blockDim.x + threadIdx.x;
    int base = t * 8;
    if (base >= E) return;
    int4 q0 = g_ed4[t * 4 + 0];
    int4 q1 = g_ed4[t * 4 + 1];
    int4 q2 = g_ed4[t * 4 + 2];
    int4 q3 = g_ed4[t * 4 + 3];
    int s[8] = {q0.x, q0.z, q1.x, q1.z, q2.x, q2.z, q3.x, q3.z};
    int d[8] = {q0.y, q0.w, q1.y, q1.w, q2.y, q2.w, q3.y, q3.w};
    float4 v[8];
#pragma unroll
    for (int k = 0; k < 8; k++) v[k] = xin[s[k]];   // 8 independent gathers (MLP)
    float a0 = v[0].x, a1 = v[0].y, a2 = v[0].z;
    int cur = d[0];
#pragma unroll
    for (int k = 1; k < 8; k++) {
        if (d[k] == cur) {
            a0 += v[k].x; a1 += v[k].y; a2 += v[k].z;
        } else {
            float* p = reinterpret_cast<float*>(&g_agg3[cur]);
            red_add_v2_f32(p, a0, a1);
            red_add_f32(p + 2, a2);
            cur = d[k]; a0 = v[k].x; a1 = v[k].y; a2 = v[k].z;
        }
    }
    float* p = reinterpret_cast<float*>(&g_agg3[cur]);
    red_add_v2_f32(p, a0, a1);
    red_add_f32(p + 2, a2);
}

__global__ void k_edge_s8(int E) {
    int t = blockIdx.x * blockDim.x + threadIdx.x;
    int base = t * 8;
    if (base >= E) return;
    int4 q0 = g_ed4[t * 4 + 0];
    int4 q1 = g_ed4[t * 4 + 1];
    int4 q2 = g_ed4[t * 4 + 2];
    int4 q3 = g_ed4[t * 4 + 3];
    int s[8] = {q0.x, q0.z, q1.x, q1.z, q2.x, q2.z, q3.x, q3.z};
    int d[8] = {q0.y, q0.w, q1.y, q1.w, q2.y, q2.w, q3.y, q3.w};
    float v[8];
#pragma unroll
    for (int k = 0; k < 8; k++) v[k] = g_x1[s[k]];
    float a = v[0];
    int cur = d[0];
#pragma unroll
    for (int k = 1; k < 8; k++) {
        if (d[k] == cur) {
            a += v[k];
        } else {
            red_add_f32(&g_agg1[cur], a);
            cur = d[k]; a = v[k];
        }
    }
    red_add_f32(&g_agg1[cur], a);
}

// ---------------- node kernels ----------------

__global__ void k_node_1to3(const float* __restrict__ norm,
                            const float* __restrict__ W, const float* __restrict__ b,
                            float4* __restrict__ xout, int n) {
    int i = blockIdx.x * blockDim.x + threadIdx.x;
    if (i >= n) return;
    float nm = norm[i];
    float t = g_agg1[i] * nm;
    g_agg1[i] = 0.f;                       // ready for layer 6
    float h0 = fmaxf(fmaf(t, W[0], b[0]), 0.f);
    float h1 = fmaxf(fmaf(t, W[1], b[1]), 0.f);
    float h2 = fmaxf(fmaf(t, W[2], b[2]), 0.f);
    xout[i] = make_float4(h0 * nm, h1 * nm, h2 * nm, 0.f);
}

__global__ void k_node_3to3(const float* __restrict__ norm,
                            const float* __restrict__ W, const float* __restrict__ b,
                            float4* __restrict__ xout, int n) {
    int i = blockIdx.x * blockDim.x + threadIdx.x;
    if (i >= n) return;
    float nm = norm[i];
    float4 a = g_agg3[i];
    g_agg3[i] = make_float4(0.f, 0.f, 0.f, 0.f);
    float a0 = a.x * nm, a1 = a.y * nm, a2 = a.z * nm;
    float h0 = fmaxf(fmaf(a0, W[0], fmaf(a1, W[3], fmaf(a2, W[6], b[0]))), 0.f);
    float h1 = fmaxf(fmaf(a0, W[1], fmaf(a1, W[4], fmaf(a2, W[7], b[1]))), 0.f);
    float h2 = fmaxf(fmaf(a0, W[2], fmaf(a1, W[5], fmaf(a2, W[8], b[2]))), 0.f);
    xout[i] = make_float4(h0 * nm, h1 * nm, h2 * nm, 0.f);
}

__global__ void k_node_3to_scalar(const float* __restrict__ norm,
                                  const float* __restrict__ W5, const float* __restrict__ b5,
                                  const float* __restrict__ W6, int n) {
    int i = blockIdx.x * blockDim.x + threadIdx.x;
    if (i >= n) return;
    float nm = norm[i];
    float4 a = g_agg3[i];
    g_agg3[i] = make_float4(0.f, 0.f, 0.f, 0.f);
    float a0 = a.x * nm, a1 = a.y * nm, a2 = a.z * nm;
    float h0 = fmaxf(fmaf(a0, W5[0], fmaf(a1, W5[3], fmaf(a2, W5[6], b5[0]))), 0.f);
    float h1 = fmaxf(fmaf(a0, W5[1], fmaf(a1, W5[4], fmaf(a2, W5[7], b5[1]))), 0.f);
    float h2 = fmaxf(fmaf(a0, W5[2], fmaf(a1, W5[5], fmaf(a2, W5[8], b5[2]))), 0.f);
    g_x1[i] = nm * (h0 * W6[0] + h1 * W6[1] + h2 * W6[2]);   // fold W6 pre-scatter
}

__global__ void k_node_final(const float* __restrict__ norm,
                             const float* __restrict__ b6,
                             float* __restrict__ out, int n) {
    int i = blockIdx.x * blockDim.x + threadIdx.x;
    if (i >= n) return;
    out[i] = fmaxf(fmaf(norm[i], g_agg1[i], b6[0]), 0.f);
}

// ---------------- launch ----------------

extern "C" void kernel_launch(void* const* d_in, const int* in_sizes, int n_in,
                              void* d_out, int out_size) {
    const int* big_i[2] = {nullptr, nullptr};
    const float* big_f[2] = {nullptr, nullptr};
    const float* small[12] = {nullptr};
    int ni = 0, nf = 0, ns = 0;
    int N = 0, E = 0;
    for (int i = 0; i < n_in; i++) {
        int sz = in_sizes[i];
        if (sz >= 10000000) {
            if (ni < 2) { big_i[ni++] = (const int*)d_in[i]; E = sz; }
        } else if (sz >= 100000) {
            if (nf < 2) { big_f[nf++] = (const float*)d_in[i]; N = sz; }
        } else {
            if (ns < 12) small[ns++] = (const float*)d_in[i];
        }
    }
    const float* feat = big_f[0];
    const float* norm = big_f[1];
    const int* src = big_i[0];
    const int* dst = big_i[1];
    const float *W1 = small[0], *b1 = small[1];
    const float *W2 = small[2], *b2 = small[3];
    const float *W3 = small[4], *b3 = small[5];
    const float *W4 = small[6], *b4 = small[7];
    const float *W5 = small[8], *b5 = small[9];
    const float *W6 = small[10], *b6 = small[11];
    float* out = (float*)d_out;

    const int TB = 256;
    int gn = (N + TB - 1) / TB;
    int ge = (E + TB - 1) / TB;
    int ge8 = (E / 8 + TB - 1) / TB;       // E = 16M, divisible by 8
    int nscan = (N + SCAN_BLOCK_ELEMS - 1) / SCAN_BLOCK_ELEMS;

    // build dst-sorted edge list
    k_init<<<gn, TB>>>(feat, norm, N);
    k_hist<<<ge, TB>>>(dst, E);
    k_scanA<<<nscan, SCAN_THREADS>>>(N);
    k_scanB<<<1, SCAN_THREADS>>>(nscan);
    k_scanC<<<gn, TB>>>(N, E);
    k_scatter<<<ge, TB>>>(src, dst, E);

    // 6 layers: flat edge-parallel scatter (run-combined reds) + fused node transform
    k_edge_s8<<<ge8, TB>>>(E);
    k_node_1to3<<<gn, TB>>>(norm, W1, b1, g_x3a, N);
    k_edge_v8<<<ge8, TB>>>(g_x3a, E);
    k_node_3to3<<<gn, TB>>>(norm, W2, b2, g_x3b, N);
    k_edge_v8<<<ge8, TB>>>(g_x3b, E);
    k_node_3to3<<<gn, TB>>>(norm, W3, b3, g_x3a, N);
    k_edge_v8<<<ge8, TB>>>(g_x3a, E);
    k_node_3to3<<<gn, TB>>>(norm, W4, b4, g_x3b, N);
    k_edge_v8<<<ge8, TB>>>(g_x3b, E);
    k_node_3to_scalar<<<gn, TB>>>(norm, W5, b5, W6, N);
    k_edge_s8<<<ge8, TB>>>(E);
    k_node_final<<<gn, TB>>>(norm, b6, out, N);
}

// round 4
// speedup vs baseline: 21.6337x; 21.6337x over previous
#include <cuda_runtime.h>
#include <cuda_bf16.h>
#include <stdint.h>

// GCNProtein: 6-layer GCN, 1M nodes, 16M edges, dims 1->3->3->3->3->3->1.
// Round 4: revert to the proven round-1 flat edge-parallel design (1.02 ms),
// no build phase. Changes vs round 1:
//   - vector scatter uses ONE red.global.add.v4.f32 per edge (w lane is 0)
//     instead of v2+scalar: halves L2 atomic ops per edge.
//   - edge kernels take 4 edges/thread with int4 index loads: 4x fewer index
//     load instructions through the saturated LTS, 4-wide MLP on gathers/reds.

#define NMAX 1000000

__device__ float4 g_x3[NMAX];    // 3-wide messages (padded to float4), layers 2-5
__device__ float4 g_agg3[NMAX];  // 3-wide accumulators (w stays 0)
__device__ float  g_x1[NMAX];    // scalar messages, layers 1 and 6
__device__ float  g_agg1[NMAX];  // scalar accumulator

__device__ __forceinline__ void red_add_f32(float* p, float v) {
    asm volatile("red.global.add.f32 [%0], %1;" :: "l"(p), "f"(v) : "memory");
}
__device__ __forceinline__ void red_add_v4_f32(float4* p, float4 v) {
    asm volatile("red.global.add.v4.f32 [%0], {%1, %2, %3, %4};"
                 :: "l"(p), "f"(v.x), "f"(v.y), "f"(v.z), "f"(v.w) : "memory");
}

// ---------------- node kernels ----------------

// layer 1 prologue: x1 = feat*norm ; agg1 = 0
__global__ void k_init(const float* __restrict__ feat, const float* __restrict__ norm, int n) {
    int i = blockIdx.x * blockDim.x + threadIdx.x;
    if (i < n) {
        g_x1[i] = feat[i] * norm[i];
        g_agg1[i] = 0.f;
    }
}

// after layer-1 scatter: h = relu((agg1*norm)*W1 + b1)  (W1 is 1x3)
// then prep layer 2: x3 = h*norm ; agg3 = 0
__global__ void k_node_1to3(const float* __restrict__ norm,
                            const float* __restrict__ W, const float* __restrict__ b, int n) {
    int i = blockIdx.x * blockDim.x + threadIdx.x;
    if (i >= n) return;
    float nm = norm[i];
    float t = g_agg1[i] * nm;
    float h0 = fmaxf(fmaf(t, W[0], b[0]), 0.f);
    float h1 = fmaxf(fmaf(t, W[1], b[1]), 0.f);
    float h2 = fmaxf(fmaf(t, W[2], b[2]), 0.f);
    g_x3[i] = make_float4(h0 * nm, h1 * nm, h2 * nm, 0.f);
    g_agg3[i] = make_float4(0.f, 0.f, 0.f, 0.f);
}

// after layer-l scatter (l in 2..4): h = relu((agg3*norm)@W + b)  (W is 3x3)
// then prep next layer: x3 = h*norm ; agg3 = 0
__global__ void k_node_3to3(const float* __restrict__ norm,
                            const float* __restrict__ W, const float* __restrict__ b, int n) {
    int i = blockIdx.x * blockDim.x + threadIdx.x;
    if (i >= n) return;
    float nm = norm[i];
    float4 a = g_agg3[i];
    float a0 = a.x * nm, a1 = a.y * nm, a2 = a.z * nm;
    float h0 = fmaxf(fmaf(a0, W[0], fmaf(a1, W[3], fmaf(a2, W[6], b[0]))), 0.f);
    float h1 = fmaxf(fmaf(a0, W[1], fmaf(a1, W[4], fmaf(a2, W[7], b[1]))), 0.f);
    float h2 = fmaxf(fmaf(a0, W[2], fmaf(a1, W[5], fmaf(a2, W[8], b[2]))), 0.f);
    g_x3[i] = make_float4(h0 * nm, h1 * nm, h2 * nm, 0.f);
    g_agg3[i] = make_float4(0.f, 0.f, 0.f, 0.f);
}

// after layer-5 scatter: h5 = relu((agg3*norm)@W5 + b5), fold W6 (3x1):
// x1 = norm*(h5@W6) ; agg1 = 0
__global__ void k_node_3to_scalar(const float* __restrict__ norm,
                                  const float* __restrict__ W5, const float* __restrict__ b5,
                                  const float* __restrict__ W6, int n) {
    int i = blockIdx.x * blockDim.x + threadIdx.x;
    if (i >= n) return;
    float nm = norm[i];
    float4 a = g_agg3[i];
    float a0 = a.x * nm, a1 = a.y * nm, a2 = a.z * nm;
    float h0 = fmaxf(fmaf(a0, W5[0], fmaf(a1, W5[3], fmaf(a2, W5[6], b5[0]))), 0.f);
    float h1 = fmaxf(fmaf(a0, W5[1], fmaf(a1, W5[4], fmaf(a2, W5[7], b5[1]))), 0.f);
    float h2 = fmaxf(fmaf(a0, W5[2], fmaf(a1, W5[5], fmaf(a2, W5[8], b5[2]))), 0.f);
    g_x1[i] = nm * (h0 * W6[0] + h1 * W6[1] + h2 * W6[2]);
    g_agg1[i] = 0.f;
}

// after layer-6 scatter: out = relu(norm*agg1 + b6)
__global__ void k_node_final(const float* __restrict__ norm,
                             const float* __restrict__ b6,
                             float* __restrict__ out, int n) {
    int i = blockIdx.x * blockDim.x + threadIdx.x;
    if (i >= n) return;
    out[i] = fmaxf(fmaf(norm[i], g_agg1[i], b6[0]), 0.f);
}

// ---------------- edge kernels (4 edges/thread, int4 index loads) ----------------

// scalar scatter: agg1[dst] += x1[src], 4 edges per thread
__global__ void k_edge_s4(const int4* __restrict__ src4, const int4* __restrict__ dst4, int nq) {
    int t = blockIdx.x * blockDim.x + threadIdx.x;
    if (t >= nq) return;
    int4 s = src4[t];
    int4 d = dst4[t];
    float v0 = g_x1[s.x];
    float v1 = g_x1[s.y];
    float v2 = g_x1[s.z];
    float v3 = g_x1[s.w];
    red_add_f32(&g_agg1[d.x], v0);
    red_add_f32(&g_agg1[d.y], v1);
    red_add_f32(&g_agg1[d.z], v2);
    red_add_f32(&g_agg1[d.w], v3);
}

// 3-wide scatter: agg3[dst] += x3[src] via one v4 red per edge (w lane adds 0)
__global__ void k_edge_v4(const int4* __restrict__ src4, const int4* __restrict__ dst4, int nq) {
    int t = blockIdx.x * blockDim.x + threadIdx.x;
    if (t >= nq) return;
    int4 s = src4[t];
    int4 d = dst4[t];
    float4 v0 = g_x3[s.x];
    float4 v1 = g_x3[s.y];
    float4 v2 = g_x3[s.z];
    float4 v3 = g_x3[s.w];
    red_add_v4_f32(&g_agg3[d.x], v0);
    red_add_v4_f32(&g_agg3[d.y], v1);
    red_add_v4_f32(&g_agg3[d.z], v2);
    red_add_v4_f32(&g_agg3[d.w], v3);
}

// ---------------- launch ----------------

extern "C" void kernel_launch(void* const* d_in, const int* in_sizes, int n_in,
                              void* d_out, int out_size) {
    // Identify inputs by element count:
    //   ~16M ints  -> src, dst (in order)
    //   ~1M floats -> feat, norm (in order)
    //   small      -> W1,b1,...,W6,b6 (in order)
    const int* big_i[2] = {nullptr, nullptr};
    const float* big_f[2] = {nullptr, nullptr};
    const float* small[12] = {nullptr};
    int ni = 0, nf = 0, ns = 0;
    int N = 0, E = 0;
    for (int i = 0; i < n_in; i++) {
        int sz = in_sizes[i];
        if (sz >= 10000000) {
            if (ni < 2) { big_i[ni++] = (const int*)d_in[i]; E = sz; }
        } else if (sz >= 100000) {
            if (nf < 2) { big_f[nf++] = (const float*)d_in[i]; N = sz; }
        } else {
            if (ns < 12) small[ns++] = (const float*)d_in[i];
        }
    }
    const float* feat = big_f[0];
    const float* norm = big_f[1];
    const int4* src4 = (const int4*)big_i[0];
    const int4* dst4 = (const int4*)big_i[1];
    const float *W1 = small[0], *b1 = small[1];
    const float *W2 = small[2], *b2 = small[3];
    const float *W3 = small[4], *b3 = small[5];
    const float *W4 = small[6], *b4 = small[7];
    const float *W5 = small[8], *b5 = small[9];
    const float *W6 = small[10], *b6 = small[11];
    float* out = (float*)d_out;

    const int TB = 256;
    int gn = (N + TB - 1) / TB;
    int nq = E / 4;                      // E = 16M, divisible by 4
    int gq = (nq + TB - 1) / TB;

    // L1 (scalar messages)
    k_init<<<gn, TB>>>(feat, norm, N);
    k_edge_s4<<<gq, TB>>>(src4, dst4, nq);
    k_node_1to3<<<gn, TB>>>(norm, W1, b1, N);
    // L2..L4 (3-wide)
    k_edge_v4<<<gq, TB>>>(src4, dst4, nq);
    k_node_3to3<<<gn, TB>>>(norm, W2, b2, N);
    k_edge_v4<<<gq, TB>>>(src4, dst4, nq);
    k_node_3to3<<<gn, TB>>>(norm, W3, b3, N);
    k_edge_v4<<<gq, TB>>>(src4, dst4, nq);
    k_node_3to3<<<gn, TB>>>(norm, W4, b4, N);
    // L5 (3-wide scatter, then fold W6 so L6 messages are scalar)
    k_edge_v4<<<gq, TB>>>(src4, dst4, nq);
    k_node_3to_scalar<<<gn, TB>>>(norm, W5, b5, W6, N);
    // L6 (scalar)
    k_edge_s4<<<gq, TB>>>(src4, dst4, nq);
    k_node_final<<<gn, TB>>>(norm, b6, out, N);
}